// round 16
// baseline (speedup 1.0000x reference)
#include <cuda_runtime.h>
#include <cuda_fp16.h>
#include <cstdint>

// ============================================================================
// Problem constants
// ============================================================================
static constexpr int M_TOK = 1024;
static constexpr int N_OUT = 4096;
static constexpr int K_IN  = 4096;

// Scratch (device globals: allocation-free per harness rules)
__device__ __align__(16) __half g_W[(size_t)N_OUT * K_IN];  // 32 MB  f16(w*scale)
__device__ __align__(16) __half g_X[(size_t)M_TOK * K_IN];  // 8 MB   f16(x)

#define DEV __device__ __forceinline__

// ============================================================================
// PTX helpers (baseline ISA only: sm_80-class, safe on compute_103)
// ============================================================================
DEV uint32_t smem_u32(const void* p) {
    uint32_t a;
    asm("{ .reg .u64 t; cvta.to.shared.u64 t, %1; cvt.u32.u64 %0, t; }"
        : "=r"(a) : "l"(p));
    return a;
}

DEV void cp_async16(uint32_t dst, const void* src) {
    asm volatile("cp.async.cg.shared.global [%0], [%1], 16;"
                 :: "r"(dst), "l"(src));
}
DEV void cp_commit() { asm volatile("cp.async.commit_group;" ::: "memory"); }
template <int N> DEV void cp_wait() {
    asm volatile("cp.async.wait_group %0;" :: "n"(N) : "memory");
}

DEV void ldsm_x4(uint32_t* r, uint32_t addr) {
    asm volatile("ldmatrix.sync.aligned.m8n8.x4.shared.b16 {%0,%1,%2,%3}, [%4];"
                 : "=r"(r[0]), "=r"(r[1]), "=r"(r[2]), "=r"(r[3]) : "r"(addr));
}

DEV void mma16816(float* c, const uint32_t* a, uint32_t b0, uint32_t b1) {
    asm volatile(
        "mma.sync.aligned.m16n8k16.row.col.f32.f16.f16.f32 "
        "{%0,%1,%2,%3}, {%4,%5,%6,%7}, {%8,%9}, {%0,%1,%2,%3};"
        : "+f"(c[0]), "+f"(c[1]), "+f"(c[2]), "+f"(c[3])
        : "r"(a[0]), "r"(a[1]), "r"(a[2]), "r"(a[3]), "r"(b0), "r"(b1));
}

// ============================================================================
// Inline weight dtype detection from the first 32 bytes (L1-broadcast).
// 8 int32 words all in [-2,1] <=> harness promoted int8 -> int32.
// Returns: 0 = int8, 1 = int32, 2 = float32. Uniform across all threads.
// ============================================================================
DEV int detect_mode(const void* wq) {
    const int4* p = reinterpret_cast<const int4*>(wq);
    int4 v0 = __ldg(p), v1 = __ldg(p + 1);
    int w[8] = {v0.x, v0.y, v0.z, v0.w, v1.x, v1.y, v1.z, v1.w};
    bool ok32 = true, okf = true;
#pragma unroll
    for (int j = 0; j < 8; j++) {
        if (w[j] < -2 || w[j] > 1) ok32 = false;
        float f = __int_as_float(w[j]);
        if (!(f == -2.0f || f == -1.0f || f == 0.0f || f == 1.0f)) okf = false;
    }
    return ok32 ? 1 : (okf ? 2 : 0);
}

// ============================================================================
// Fused prep: blocks [0, 8192) fold scales into W; [8192, 10240) convert x.
// ============================================================================
__global__ void prep_all_kernel(const void* __restrict__ wq_raw,
                                const float* __restrict__ scales,
                                const float* __restrict__ x) {
    if (blockIdx.x < 8192) {
        int idx = blockIdx.x * 256 + threadIdx.x;      // 2,097,152 threads
        int n  = idx >> 9;                             // row 0..4095
        int kc = (idx & 511) << 3;                     // k start (8 elems)
        float s = scales[(n << 5) + (kc >> 7)];        // per-(n, k/128) scale
        size_t off = (size_t)n * K_IN + kc;
        int mode = detect_mode(wq_raw);                // uniform, L1-broadcast

        float w[8];
        if (mode == 1) {                               // int32-promoted weights
            const int4* p = reinterpret_cast<const int4*>((const int*)wq_raw + off);
            int4 v0 = p[0], v1 = p[1];
            w[0] = (float)v0.x; w[1] = (float)v0.y; w[2] = (float)v0.z; w[3] = (float)v0.w;
            w[4] = (float)v1.x; w[5] = (float)v1.y; w[6] = (float)v1.z; w[7] = (float)v1.w;
        } else if (mode == 2) {                        // float32-promoted weights
            const float4* p = reinterpret_cast<const float4*>((const float*)wq_raw + off);
            float4 v0 = p[0], v1 = p[1];
            w[0] = v0.x; w[1] = v0.y; w[2] = v0.z; w[3] = v0.w;
            w[4] = v1.x; w[5] = v1.y; w[6] = v1.z; w[7] = v1.w;
        } else {                                       // true int8 weights
            long long v = *reinterpret_cast<const long long*>((const signed char*)wq_raw + off);
#pragma unroll
            for (int j = 0; j < 4; j++) {
                w[2*j]   = (float)(signed char)(v >> (16 * j));
                w[2*j+1] = (float)(signed char)(v >> (16 * j + 8));
            }
        }

        __align__(16) __half2 o[4];
#pragma unroll
        for (int j = 0; j < 4; j++)
            o[j] = __floats2half2_rn(w[2*j] * s, w[2*j+1] * s);
        *reinterpret_cast<uint4*>(&g_W[off]) = *reinterpret_cast<const uint4*>(o);
    } else {
        int idx = (blockIdx.x - 8192) * 256 + threadIdx.x;   // 524,288 threads
        const float4* src = reinterpret_cast<const float4*>(x) + (size_t)idx * 2;
        float4 a = src[0], b = src[1];
        __align__(16) __half2 o[4];
        o[0] = __floats2half2_rn(a.x, a.y);
        o[1] = __floats2half2_rn(a.z, a.w);
        o[2] = __floats2half2_rn(b.x, b.y);
        o[3] = __floats2half2_rn(b.z, b.w);
        *reinterpret_cast<uint4*>(&g_X[(size_t)idx * 8]) =
            *reinterpret_cast<const uint4*>(o);
    }
}

// ============================================================================
// HMMA GEMM: out[M,N] = Xh[M,K] @ Wh[N,K]^T, fp32 accumulate
//   CTA 128x256, BK=64, 8 warps (2x4), warp tile 64x64 (acc = 128 regs)
//   3-stage cp.async pipeline (wait_group 1), 1 CTA/SM, grid 128 (single wave)
//   Rationale: 64x64 warp tile cuts LDSM bytes/output 1.5 -> 1.0 (crossbar
//   was co-bottleneck at ~55us, serializing with the ~56us tensor stream).
// ============================================================================
static constexpr int BM = 128, BN = 256, BK = 64;
static constexpr int NIT = K_IN / BK;                  // 64 k-iterations
static constexpr int NSTAGE = 3;
static constexpr int A_BYTES = BM * 128;               // 16 KB (128 rows x 128B)
static constexpr int B_BYTES = BN * 128;               // 32 KB (256 rows x 128B)
static constexpr int STAGE_BYTES = A_BYTES + B_BYTES;  // 48 KB
static constexpr int SMEM_DYN = 1024 + NSTAGE * STAGE_BYTES;  // 145.4 KB (1 CTA/SM)

// Per-row swizzle for 128B rows: byte_in_row ^= (row & 7) << 4.

DEV void load_stage(int tid, uint32_t sbase, const __half* Ag, const __half* Bg, int kk) {
#pragma unroll
    for (int i = 0; i < 12; i++) {
        int t   = tid + i * 256;         // 0..3071 16B chunks (A:0..1023, B:1024..3071)
        int isB = t >= 1024;
        int r   = isB ? ((t - 1024) >> 3) : (t >> 3);  // A row 0..127 / B row 0..255
        int c   = t & 7;                 // 16B chunk within 128B row
        const __half* src = (isB ? Bg : Ag) + (size_t)r * K_IN + kk * BK + c * 8;
        uint32_t off = (uint32_t)(r * 128 + (((uint32_t)c * 16) ^ (((uint32_t)r & 7) << 4)));
        uint32_t dst = sbase + (uint32_t)(isB ? A_BYTES : 0) + off;
        cp_async16(dst, src);
    }
    cp_commit();
}

__global__ void __launch_bounds__(256, 1) gemm_kernel(float* __restrict__ out) {
    extern __shared__ char smem_raw[];
    uint32_t base = (smem_u32(smem_raw) + 1023u) & ~1023u;  // 1024-align

    int tid  = threadIdx.x;
    int wid  = tid >> 5;
    int lane = tid & 31;
    int wm   = wid >> 2;        // 0..1 -> 64-row strip
    int wn   = wid & 3;         // 0..3 -> 64-col strip

    const __half* Ag = g_X + (size_t)blockIdx.y * BM * K_IN;
    const __half* Bg = g_W + (size_t)blockIdx.x * BN * K_IN;

    float acc[4][8][4] = {};    // [m16 tile][n8 tile][frag] = 128 regs

    // ldmatrix addressing: all fragment rows r satisfy r&7 == lrow&7, so the
    // swizzle XOR collapses to per-thread constants (see round-15 derivation).
    int lrow = lane & 15;                       // row within the 16-row group
    uint32_t lkb = (uint32_t)((lane >> 4) << 4);// k-byte half: 0 or 16
    uint32_t msk = (uint32_t)((lrow & 7) << 4);

    uint32_t kof[4];
#pragma unroll
    for (int ks = 0; ks < 4; ks++)
        kof[ks] = ((uint32_t)(ks * 32) + lkb) ^ msk;

    uint32_t offA[4], offB[4];
#pragma unroll
    for (int mi = 0; mi < 4; mi++)
        offA[mi] = (uint32_t)((wm * 64 + mi * 16 + lrow) * 128);
#pragma unroll
    for (int nj = 0; nj < 4; nj++)
        offB[nj] = (uint32_t)(A_BYTES + (wn * 64 + nj * 16 + lrow) * 128);

    // Prologue: fill stages 0,1
    load_stage(tid, base + 0 * STAGE_BYTES, Ag, Bg, 0);
    load_stage(tid, base + 1 * STAGE_BYTES, Ag, Bg, 1);

    int s = 0;                       // slot of iteration it (cycles mod 3)
    for (int it = 0; it < NIT; it++) {
        if (it < NIT - 1) cp_wait<1>();   // group `it` done, `it+1` may fly
        else              cp_wait<0>();   // last iter: drain everything
        __syncthreads();

        uint32_t St = base + (uint32_t)s * STAGE_BYTES;

        // Issue next-next tile load before compute so it overlaps the MMAs.
        // Slot (it+2)%3 == (it-1)%3: its readers finished before the sync above.
        if (it + 2 < NIT) {
            int ns = s + 2; if (ns >= 3) ns -= 3;
            load_stage(tid, base + (uint32_t)ns * STAGE_BYTES, Ag, Bg, it + 2);
        }

#pragma unroll
        for (int ks = 0; ks < 4; ks++) {              // 4 x k16 per BK=64
            uint32_t a[4][4], b[4][4];
#pragma unroll
            for (int mi = 0; mi < 4; mi++)
                ldsm_x4(a[mi], St + offA[mi] + kof[ks]);
#pragma unroll
            for (int nj = 0; nj < 4; nj++)
                ldsm_x4(b[nj], St + offB[nj] + kof[ks]);
#pragma unroll
            for (int mi = 0; mi < 4; mi++)
#pragma unroll
                for (int ni = 0; ni < 8; ni++)
                    mma16816(acc[mi][ni], a[mi],
                             b[ni >> 1][ni & 1], b[ni >> 1][(ni & 1) + 2]);
        }

        if (++s >= 3) s -= 3;
    }

    // Epilogue: c0,c1 -> row lane>>2; c2,c3 -> row lane>>2 + 8
    int rowBase = blockIdx.y * BM + wm * 64;
    int colBase = blockIdx.x * BN + wn * 64;
#pragma unroll
    for (int mi = 0; mi < 4; mi++) {
#pragma unroll
        for (int ni = 0; ni < 8; ni++) {
            int r = rowBase + mi * 16 + (lane >> 2);
            int c = colBase + ni * 8 + (lane & 3) * 2;
            float2 v0 = make_float2(acc[mi][ni][0], acc[mi][ni][1]);
            float2 v1 = make_float2(acc[mi][ni][2], acc[mi][ni][3]);
            *reinterpret_cast<float2*>(out + (size_t)r * N_OUT + c)       = v0;
            *reinterpret_cast<float2*>(out + (size_t)(r + 8) * N_OUT + c) = v1;
        }
    }
}

// ============================================================================
// Launch — bind by unique ELEMENT count, fall back to declared order.
// ============================================================================
extern "C" void kernel_launch(void* const* d_in, const int* in_sizes, int n_in,
                              void* d_out, int out_size) {
    const float* x      = nullptr;
    const void*  wq     = nullptr;
    const float* scales = nullptr;
    for (int i = 0; i < n_in; i++) {
        if      (in_sizes[i] == M_TOK * K_IN)         x      = (const float*)d_in[i];
        else if (in_sizes[i] == N_OUT * K_IN)         wq     = (const void*)d_in[i];
        else if (in_sizes[i] == N_OUT * (K_IN / 128)) scales = (const float*)d_in[i];
    }
    if (!x || !wq || !scales) {   // defensive fallback: declared order
        x      = (const float*)d_in[0];
        wq     = (const void*)d_in[1];
        scales = (const float*)d_in[2];
    }
    float* out = (float*)d_out;

    cudaFuncSetAttribute(gemm_kernel,
                         cudaFuncAttributeMaxDynamicSharedMemorySize, SMEM_DYN);

    prep_all_kernel<<<8192 + 2048, 256>>>(wq, scales, x);

    dim3 grid(N_OUT / BN, M_TOK / BM);   // (16, 8) = 128 CTAs, 1/SM, single wave
    gemm_kernel<<<grid, 256, SMEM_DYN>>>(out);
}

// round 17
// speedup vs baseline: 1.0419x; 1.0419x over previous
#include <cuda_runtime.h>
#include <cuda_fp16.h>
#include <cstdint>

// ============================================================================
// Problem constants
// ============================================================================
static constexpr int M_TOK = 1024;
static constexpr int N_OUT = 4096;
static constexpr int K_IN  = 4096;

// Scratch (device globals: allocation-free per harness rules)
__device__ __align__(16) __half g_W[(size_t)N_OUT * K_IN];  // 32 MB  f16(w*scale)
__device__ __align__(16) __half g_X[(size_t)M_TOK * K_IN];  // 8 MB   f16(x)

#define DEV __device__ __forceinline__

// ============================================================================
// PTX helpers (baseline ISA only: sm_80-class, safe on compute_103)
// ============================================================================
DEV uint32_t smem_u32(const void* p) {
    uint32_t a;
    asm("{ .reg .u64 t; cvta.to.shared.u64 t, %1; cvt.u32.u64 %0, t; }"
        : "=r"(a) : "l"(p));
    return a;
}

DEV void cp_async16(uint32_t dst, const void* src) {
    asm volatile("cp.async.cg.shared.global [%0], [%1], 16;"
                 :: "r"(dst), "l"(src));
}
DEV void cp_commit() { asm volatile("cp.async.commit_group;" ::: "memory"); }
template <int N> DEV void cp_wait() {
    asm volatile("cp.async.wait_group %0;" :: "n"(N) : "memory");
}

DEV void ldsm_x4(uint32_t* r, uint32_t addr) {
    asm volatile("ldmatrix.sync.aligned.m8n8.x4.shared.b16 {%0,%1,%2,%3}, [%4];"
                 : "=r"(r[0]), "=r"(r[1]), "=r"(r[2]), "=r"(r[3]) : "r"(addr));
}

DEV void mma16816(float* c, const uint32_t* a, uint32_t b0, uint32_t b1) {
    asm volatile(
        "mma.sync.aligned.m16n8k16.row.col.f32.f16.f16.f32 "
        "{%0,%1,%2,%3}, {%4,%5,%6,%7}, {%8,%9}, {%0,%1,%2,%3};"
        : "+f"(c[0]), "+f"(c[1]), "+f"(c[2]), "+f"(c[3])
        : "r"(a[0]), "r"(a[1]), "r"(a[2]), "r"(a[3]), "r"(b0), "r"(b1));
}

// ============================================================================
// Inline weight dtype detection from the first 32 bytes (L1-broadcast).
// 8 int32 words all in [-2,1] <=> harness promoted int8 -> int32.
// Returns: 0 = int8, 1 = int32, 2 = float32. Uniform across all threads.
// ============================================================================
DEV int detect_mode(const void* wq) {
    const int4* p = reinterpret_cast<const int4*>(wq);
    int4 v0 = __ldg(p), v1 = __ldg(p + 1);
    int w[8] = {v0.x, v0.y, v0.z, v0.w, v1.x, v1.y, v1.z, v1.w};
    bool ok32 = true, okf = true;
#pragma unroll
    for (int j = 0; j < 8; j++) {
        if (w[j] < -2 || w[j] > 1) ok32 = false;
        float f = __int_as_float(w[j]);
        if (!(f == -2.0f || f == -1.0f || f == 0.0f || f == 1.0f)) okf = false;
    }
    return ok32 ? 1 : (okf ? 2 : 0);
}

// ============================================================================
// Fused prep: blocks [0, 8192) fold scales into W; [8192, 10240) convert x.
// ============================================================================
__global__ void prep_all_kernel(const void* __restrict__ wq_raw,
                                const float* __restrict__ scales,
                                const float* __restrict__ x) {
    if (blockIdx.x < 8192) {
        int idx = blockIdx.x * 256 + threadIdx.x;      // 2,097,152 threads
        int n  = idx >> 9;                             // row 0..4095
        int kc = (idx & 511) << 3;                     // k start (8 elems)
        float s = scales[(n << 5) + (kc >> 7)];        // per-(n, k/128) scale
        size_t off = (size_t)n * K_IN + kc;
        int mode = detect_mode(wq_raw);                // uniform, L1-broadcast

        float w[8];
        if (mode == 1) {                               // int32-promoted weights
            const int4* p = reinterpret_cast<const int4*>((const int*)wq_raw + off);
            int4 v0 = p[0], v1 = p[1];
            w[0] = (float)v0.x; w[1] = (float)v0.y; w[2] = (float)v0.z; w[3] = (float)v0.w;
            w[4] = (float)v1.x; w[5] = (float)v1.y; w[6] = (float)v1.z; w[7] = (float)v1.w;
        } else if (mode == 2) {                        // float32-promoted weights
            const float4* p = reinterpret_cast<const float4*>((const float*)wq_raw + off);
            float4 v0 = p[0], v1 = p[1];
            w[0] = v0.x; w[1] = v0.y; w[2] = v0.z; w[3] = v0.w;
            w[4] = v1.x; w[5] = v1.y; w[6] = v1.z; w[7] = v1.w;
        } else {                                       // true int8 weights
            long long v = *reinterpret_cast<const long long*>((const signed char*)wq_raw + off);
#pragma unroll
            for (int j = 0; j < 4; j++) {
                w[2*j]   = (float)(signed char)(v >> (16 * j));
                w[2*j+1] = (float)(signed char)(v >> (16 * j + 8));
            }
        }

        __align__(16) __half2 o[4];
#pragma unroll
        for (int j = 0; j < 4; j++)
            o[j] = __floats2half2_rn(w[2*j] * s, w[2*j+1] * s);
        *reinterpret_cast<uint4*>(&g_W[off]) = *reinterpret_cast<const uint4*>(o);
    } else {
        int idx = (blockIdx.x - 8192) * 256 + threadIdx.x;   // 524,288 threads
        const float4* src = reinterpret_cast<const float4*>(x) + (size_t)idx * 2;
        float4 a = src[0], b = src[1];
        __align__(16) __half2 o[4];
        o[0] = __floats2half2_rn(a.x, a.y);
        o[1] = __floats2half2_rn(a.z, a.w);
        o[2] = __floats2half2_rn(b.x, b.y);
        o[3] = __floats2half2_rn(b.z, b.w);
        *reinterpret_cast<uint4*>(&g_X[(size_t)idx * 8]) =
            *reinterpret_cast<const uint4*>(o);
    }
}

// ============================================================================
// HMMA GEMM: out[M,N] = Xh[M,K] @ Wh[N,K]^T, fp32 accumulate
//   CTA 128x128, BK=64, 8 warps (2x4), warp tile 64x32
//   3-stage cp.async pipeline (wait_group 0 at top), 2 CTAs/SM, single wave
//   CROSS-ITERATION FRAGMENT CARRY: ks=0 fragments of stage it+1 are
//   prefetched during ks=3 of iteration it, so every iteration opens with
//   16 ready MMAs instead of a post-barrier dependent ldsm chain.
// ============================================================================
static constexpr int BM = 128, BN = 128, BK = 64;
static constexpr int NIT = K_IN / BK;                  // 64 k-iterations
static constexpr int NSTAGE = 3;
static constexpr int A_BYTES = BM * 128;               // 16 KB (128 rows x 128B)
static constexpr int B_BYTES = BN * 128;               // 16 KB
static constexpr int STAGE_BYTES = A_BYTES + B_BYTES;  // 32 KB
static constexpr int SMEM_DYN = 1024 + NSTAGE * STAGE_BYTES;  // 97.25 KB; x2 < 228

// Per-row swizzle for 128B rows: byte_in_row ^= (row & 7) << 4.

DEV void load_stage(int tid, uint32_t sbase, const __half* Ag, const __half* Bg, int kk) {
#pragma unroll
    for (int i = 0; i < 8; i++) {
        int t   = tid + i * 256;         // 0..2047 16B chunks (A:0..1023, B:1024..2047)
        int isB = t >> 10;
        int r   = (t & 1023) >> 3;       // tile row 0..127
        int c   = t & 7;                 // 16B chunk within 128B row
        const __half* src = (isB ? Bg : Ag) + (size_t)r * K_IN + kk * BK + c * 8;
        uint32_t off = (uint32_t)(r * 128 + (((uint32_t)c * 16) ^ (((uint32_t)r & 7) << 4)));
        uint32_t dst = sbase + (uint32_t)isB * A_BYTES + off;
        cp_async16(dst, src);
    }
    cp_commit();
}

__global__ void __launch_bounds__(256, 2) gemm_kernel(float* __restrict__ out) {
    extern __shared__ char smem_raw[];
    uint32_t base = (smem_u32(smem_raw) + 1023u) & ~1023u;  // 1024-align

    int tid  = threadIdx.x;
    int wid  = tid >> 5;
    int lane = tid & 31;
    int wm   = wid >> 2;        // 0..1 -> 64-row strip
    int wn   = wid & 3;         // 0..3 -> 32-col strip

    const __half* Ag = g_X + (size_t)blockIdx.y * BM * K_IN;
    const __half* Bg = g_W + (size_t)blockIdx.x * BN * K_IN;

    float acc[4][4][4] = {};    // [m16 tile][n8 tile][frag] = 64 regs

    // ldmatrix addressing: all fragment rows r satisfy r&7 == lrow&7, so the
    // swizzle XOR collapses to per-thread constants.
    int lrow = lane & 15;                       // row within the 16-row group
    uint32_t lkb = (uint32_t)((lane >> 4) << 4);// k-byte half: 0 or 16
    uint32_t msk = (uint32_t)((lrow & 7) << 4);

    uint32_t kof[4];
#pragma unroll
    for (int ks = 0; ks < 4; ks++)
        kof[ks] = ((uint32_t)(ks * 32) + lkb) ^ msk;

    uint32_t offA[4], offB[2];
#pragma unroll
    for (int mi = 0; mi < 4; mi++)
        offA[mi] = (uint32_t)((wm * 64 + mi * 16 + lrow) * 128);
#pragma unroll
    for (int nj = 0; nj < 2; nj++)
        offB[nj] = (uint32_t)(A_BYTES + (wn * 32 + nj * 16 + lrow) * 128);

    // Prologue: fill stages 0,1; then preload carry fragments for it=0, ks=0.
    load_stage(tid, base + 0 * STAGE_BYTES, Ag, Bg, 0);
    load_stage(tid, base + 1 * STAGE_BYTES, Ag, Bg, 1);
    cp_wait<0>();
    __syncthreads();

    uint32_t ac[4][4], bc[2][4];     // carried ks=0 fragments (24 regs)
#pragma unroll
    for (int mi = 0; mi < 4; mi++) ldsm_x4(ac[mi], base + offA[mi] + kof[0]);
#pragma unroll
    for (int nj = 0; nj < 2; nj++) ldsm_x4(bc[nj], base + offB[nj] + kof[0]);

    int s = 0;                       // slot of iteration it (cycles mod 3)
    for (int it = 0; it < NIT; it++) {
        if (it) {
            // All issued groups (<= it+1) complete, then barrier => stage it
            // AND stage it+1 data globally visible; slot (it+2)%3's previous
            // readers are past (they read it in iter it-1, before this sync).
            cp_wait<0>();
            __syncthreads();
        }

        uint32_t St = base + (uint32_t)s * STAGE_BYTES;

        if (it + 2 < NIT) {
            int ns = s + 2; if (ns >= 3) ns -= 3;
            load_stage(tid, base + (uint32_t)ns * STAGE_BYTES, Ag, Bg, it + 2);
        }

        // ---- ks = 0: MMAs fire immediately from carried fragments ----
#pragma unroll
        for (int mi = 0; mi < 4; mi++)
#pragma unroll
            for (int ni = 0; ni < 4; ni++)
                mma16816(acc[mi][ni], ac[mi],
                         bc[ni >> 1][ni & 1], bc[ni >> 1][(ni & 1) + 2]);

        // ---- ks = 1..3: JIT fragments; at ks=3 prefetch next iter's carry ----
#pragma unroll
        for (int ks = 1; ks < 4; ks++) {
            uint32_t a[4][4], b[2][4];
#pragma unroll
            for (int mi = 0; mi < 4; mi++) ldsm_x4(a[mi], St + offA[mi] + kof[ks]);
#pragma unroll
            for (int nj = 0; nj < 2; nj++) ldsm_x4(b[nj], St + offB[nj] + kof[ks]);

            if (ks == 3 && it + 1 < NIT) {
                // Stage it+1 (slot s+1): data arrived (wait<0> at top covered
                // group it+1) and slot is not rewritten until iter it+2.
                int n1 = s + 1; if (n1 >= 3) n1 -= 3;
                uint32_t Sn = base + (uint32_t)n1 * STAGE_BYTES;
#pragma unroll
                for (int mi = 0; mi < 4; mi++) ldsm_x4(ac[mi], Sn + offA[mi] + kof[0]);
#pragma unroll
                for (int nj = 0; nj < 2; nj++) ldsm_x4(bc[nj], Sn + offB[nj] + kof[0]);
            }

#pragma unroll
            for (int mi = 0; mi < 4; mi++)
#pragma unroll
                for (int ni = 0; ni < 4; ni++)
                    mma16816(acc[mi][ni], a[mi],
                             b[ni >> 1][ni & 1], b[ni >> 1][(ni & 1) + 2]);
        }

        if (++s >= 3) s -= 3;
    }

    // Epilogue: c0,c1 -> row lane>>2; c2,c3 -> row lane>>2 + 8
    int rowBase = blockIdx.y * BM + wm * 64;
    int colBase = blockIdx.x * BN + wn * 32;
#pragma unroll
    for (int mi = 0; mi < 4; mi++) {
#pragma unroll
        for (int ni = 0; ni < 4; ni++) {
            int r = rowBase + mi * 16 + (lane >> 2);
            int c = colBase + ni * 8 + (lane & 3) * 2;
            float2 v0 = make_float2(acc[mi][ni][0], acc[mi][ni][1]);
            float2 v1 = make_float2(acc[mi][ni][2], acc[mi][ni][3]);
            *reinterpret_cast<float2*>(out + (size_t)r * N_OUT + c)       = v0;
            *reinterpret_cast<float2*>(out + (size_t)(r + 8) * N_OUT + c) = v1;
        }
    }
}

// ============================================================================
// Launch — bind by unique ELEMENT count, fall back to declared order.
// ============================================================================
extern "C" void kernel_launch(void* const* d_in, const int* in_sizes, int n_in,
                              void* d_out, int out_size) {
    const float* x      = nullptr;
    const void*  wq     = nullptr;
    const float* scales = nullptr;
    for (int i = 0; i < n_in; i++) {
        if      (in_sizes[i] == M_TOK * K_IN)         x      = (const float*)d_in[i];
        else if (in_sizes[i] == N_OUT * K_IN)         wq     = (const void*)d_in[i];
        else if (in_sizes[i] == N_OUT * (K_IN / 128)) scales = (const float*)d_in[i];
    }
    if (!x || !wq || !scales) {   // defensive fallback: declared order
        x      = (const float*)d_in[0];
        wq     = (const void*)d_in[1];
        scales = (const float*)d_in[2];
    }
    float* out = (float*)d_out;

    cudaFuncSetAttribute(gemm_kernel,
                         cudaFuncAttributeMaxDynamicSharedMemorySize, SMEM_DYN);

    prep_all_kernel<<<8192 + 2048, 256>>>(wq, scales, x);

    dim3 grid(N_OUT / BN, M_TOK / BM);   // (32, 8) = 256 CTAs, 2/SM, single wave
    gemm_kernel<<<grid, 256, SMEM_DYN>>>(out);
}